// round 1
// baseline (speedup 1.0000x reference)
#include <cuda_runtime.h>

#define DM 2048   // d_model
#define BATCH 2048
#define NT 64     // num transforms
#define RK 32     // rank

// Scratch (static device arrays; no allocation allowed)
__device__ float g_GVx[BATCH * DM];   // gated Vx, row-major (b, k), k = n*32 + r
__device__ float g_norms[2 * NT];     // [0..63] = ||U_n||_F, [64..127] = ||V_n||_F

// ---------------------------------------------------------------------------
// Gate kernel: pre[b,n] = dot(x[b,:], enc[n,:]) - bias[n]; gate = relu(pre).
// M=2048, N=64, K=2048. BM=32, BN=64, BK=32, 256 threads, 64 blocks.
// ---------------------------------------------------------------------------
__global__ __launch_bounds__(256) void gate_kernel(
    const float* __restrict__ x, const float* __restrict__ enc,
    const float* __restrict__ bias, float* __restrict__ gate)
{
    __shared__ __align__(16) float As[32][36];   // As[k][m], m = local b row
    __shared__ __align__(16) float Es[32][68];   // Es[k][n]

    const int tid = threadIdx.x;
    const int tx = tid & 15;        // -> n block (4 cols each)
    const int ty = tid >> 4;        // -> m block (2 rows each)
    const int b0 = blockIdx.x * 32;
    const int f4 = tid & 7;
    const int lrow = tid >> 3;      // 0..31

    float acc[2][4];
    #pragma unroll
    for (int i = 0; i < 2; i++)
        #pragma unroll
        for (int j = 0; j < 4; j++) acc[i][j] = 0.0f;

    for (int d0 = 0; d0 < DM; d0 += 32) {
        // x tile: 32 rows x 32 cols, store transposed As[d][b]
        {
            float4 v = *(const float4*)(x + (b0 + lrow) * DM + d0 + f4 * 4);
            As[f4*4+0][lrow] = v.x; As[f4*4+1][lrow] = v.y;
            As[f4*4+2][lrow] = v.z; As[f4*4+3][lrow] = v.w;
        }
        // enc tile: 64 rows x 32 cols, store transposed Es[d][n]
        #pragma unroll
        for (int p = 0; p < 2; p++) {
            int row = p * 32 + lrow;
            float4 v = *(const float4*)(enc + row * DM + d0 + f4 * 4);
            Es[f4*4+0][row] = v.x; Es[f4*4+1][row] = v.y;
            Es[f4*4+2][row] = v.z; Es[f4*4+3][row] = v.w;
        }
        __syncthreads();
        #pragma unroll
        for (int kk = 0; kk < 32; kk++) {
            float a0 = As[kk][ty*2 + 0];
            float a1 = As[kk][ty*2 + 1];
            float4 e = *(const float4*)&Es[kk][tx*4];
            acc[0][0] += a0 * e.x; acc[0][1] += a0 * e.y;
            acc[0][2] += a0 * e.z; acc[0][3] += a0 * e.w;
            acc[1][0] += a1 * e.x; acc[1][1] += a1 * e.y;
            acc[1][2] += a1 * e.z; acc[1][3] += a1 * e.w;
        }
        __syncthreads();
    }
    #pragma unroll
    for (int i = 0; i < 2; i++) {
        int b = b0 + ty*2 + i;
        #pragma unroll
        for (int j = 0; j < 4; j++) {
            int n = tx*4 + j;
            float p = acc[i][j] - bias[n];
            gate[b * NT + n] = (p > 0.0f) ? p : 0.0f;
        }
    }
}

// ---------------------------------------------------------------------------
// Frobenius norms
// ---------------------------------------------------------------------------
__global__ __launch_bounds__(256) void norm_kernel(
    const float* __restrict__ Uw, const float* __restrict__ Vw)
{
    int bid = blockIdx.x;  // 0..127
    const float* base = (bid < NT) ? (Uw + bid * (DM * RK))
                                   : (Vw + (bid - NT) * (RK * DM));
    const float4* p4 = (const float4*)base;
    float s = 0.0f;
    for (int i = threadIdx.x; i < (DM * RK) / 4; i += 256) {
        float4 v = p4[i];
        s += v.x*v.x + v.y*v.y + v.z*v.z + v.w*v.w;
    }
    __shared__ float red[256];
    red[threadIdx.x] = s;
    __syncthreads();
    for (int off = 128; off > 0; off >>= 1) {
        if (threadIdx.x < off) red[threadIdx.x] += red[threadIdx.x + off];
        __syncthreads();
    }
    if (threadIdx.x == 0) g_norms[bid] = sqrtf(red[0]);
}

__global__ void frob_kernel(float* __restrict__ frob)
{
    int n = threadIdx.x;  // 64 threads
    frob[n] = g_norms[n] * g_norms[NT + n] * (1.0f / 256.0f);  // /sqrt(2048*32)
}

// ---------------------------------------------------------------------------
// GEMM 1: GVx[b,k] = gate[b, k>>5] * sum_d x[b,d] * Vflat[k,d]
// A = x (row-major b,d), B = Vflat (row-major k,d) -> "NT" gemm.
// BM=BN=128, BK=32, 256 threads, 8x8 microtile. grid (16,16).
// ---------------------------------------------------------------------------
__global__ __launch_bounds__(256) void gemm_vx(
    const float* __restrict__ x, const float* __restrict__ Vw,
    const float* __restrict__ gate)
{
    __shared__ __align__(16) float As[32][132];  // As[d][b]
    __shared__ __align__(16) float Bs[32][132];  // Bs[d][k]

    const int tid = threadIdx.x;
    const int tx = tid & 15, ty = tid >> 4;
    const int k0 = blockIdx.x * 128;
    const int b0 = blockIdx.y * 128;
    const int f4 = tid & 7, lrow = tid >> 3;

    float acc[8][8];
    #pragma unroll
    for (int i = 0; i < 8; i++)
        #pragma unroll
        for (int j = 0; j < 8; j++) acc[i][j] = 0.0f;

    for (int d0 = 0; d0 < DM; d0 += 32) {
        #pragma unroll
        for (int p = 0; p < 4; p++) {
            int row = p * 32 + lrow;
            float4 va = *(const float4*)(x  + (b0 + row) * DM + d0 + f4 * 4);
            As[f4*4+0][row] = va.x; As[f4*4+1][row] = va.y;
            As[f4*4+2][row] = va.z; As[f4*4+3][row] = va.w;
            float4 vb = *(const float4*)(Vw + (k0 + row) * DM + d0 + f4 * 4);
            Bs[f4*4+0][row] = vb.x; Bs[f4*4+1][row] = vb.y;
            Bs[f4*4+2][row] = vb.z; Bs[f4*4+3][row] = vb.w;
        }
        __syncthreads();
        #pragma unroll
        for (int kk = 0; kk < 32; kk++) {
            float4 a0 = *(const float4*)&As[kk][ty*8];
            float4 a1 = *(const float4*)&As[kk][ty*8 + 4];
            float4 c0 = *(const float4*)&Bs[kk][tx*8];
            float4 c1 = *(const float4*)&Bs[kk][tx*8 + 4];
            float a[8] = {a0.x,a0.y,a0.z,a0.w,a1.x,a1.y,a1.z,a1.w};
            float bb[8] = {c0.x,c0.y,c0.z,c0.w,c1.x,c1.y,c1.z,c1.w};
            #pragma unroll
            for (int i = 0; i < 8; i++)
                #pragma unroll
                for (int j = 0; j < 8; j++)
                    acc[i][j] += a[i] * bb[j];
        }
        __syncthreads();
    }

    // epilogue: gate. Each thread's 8 cols lie in a single transform n.
    const int n = (k0 + tx*8) >> 5;
    #pragma unroll
    for (int i = 0; i < 8; i++) {
        int b = b0 + ty*8 + i;
        float g = gate[b * NT + n];
        float4 o0 = make_float4(acc[i][0]*g, acc[i][1]*g, acc[i][2]*g, acc[i][3]*g);
        float4 o1 = make_float4(acc[i][4]*g, acc[i][5]*g, acc[i][6]*g, acc[i][7]*g);
        *(float4*)(g_GVx + b * DM + k0 + tx*8)     = o0;
        *(float4*)(g_GVx + b * DM + k0 + tx*8 + 4) = o1;
    }
}

// ---------------------------------------------------------------------------
// GEMM 2: out[b,d] = sum_k GVx[b,k] * W[k,d],  W[k,d] = U[n, d, r], k = n*32+r.
// BK=32 aligned so each k-step is exactly one transform n; B-tile load
// U[n, d0:d0+128, 0:32] is fully coalesced (32 contiguous floats per d).
// ---------------------------------------------------------------------------
__global__ __launch_bounds__(256) void gemm_out(
    const float* __restrict__ Uw, float* __restrict__ out)
{
    __shared__ __align__(16) float As[32][132];  // As[k][b]
    __shared__ __align__(16) float Bs[32][132];  // Bs[r][d]

    const int tid = threadIdx.x;
    const int tx = tid & 15, ty = tid >> 4;
    const int d0 = blockIdx.x * 128;
    const int b0 = blockIdx.y * 128;
    const int f4 = tid & 7, lrow = tid >> 3;

    float acc[8][8];
    #pragma unroll
    for (int i = 0; i < 8; i++)
        #pragma unroll
        for (int j = 0; j < 8; j++) acc[i][j] = 0.0f;

    for (int n = 0; n < NT; n++) {          // 64 k-steps of 32
        const int kbase = n * 32;
        #pragma unroll
        for (int p = 0; p < 4; p++) {
            int row = p * 32 + lrow;
            float4 va = *(const float4*)(g_GVx + (b0 + row) * DM + kbase + f4 * 4);
            As[f4*4+0][row] = va.x; As[f4*4+1][row] = va.y;
            As[f4*4+2][row] = va.z; As[f4*4+3][row] = va.w;
            // U[n, d0+row, f4*4 .. +3]
            float4 vb = *(const float4*)(Uw + n * (DM * RK) + (d0 + row) * RK + f4 * 4);
            Bs[f4*4+0][row] = vb.x; Bs[f4*4+1][row] = vb.y;
            Bs[f4*4+2][row] = vb.z; Bs[f4*4+3][row] = vb.w;
        }
        __syncthreads();
        #pragma unroll
        for (int kk = 0; kk < 32; kk++) {
            float4 a0 = *(const float4*)&As[kk][ty*8];
            float4 a1 = *(const float4*)&As[kk][ty*8 + 4];
            float4 c0 = *(const float4*)&Bs[kk][tx*8];
            float4 c1 = *(const float4*)&Bs[kk][tx*8 + 4];
            float a[8] = {a0.x,a0.y,a0.z,a0.w,a1.x,a1.y,a1.z,a1.w};
            float bb[8] = {c0.x,c0.y,c0.z,c0.w,c1.x,c1.y,c1.z,c1.w};
            #pragma unroll
            for (int i = 0; i < 8; i++)
                #pragma unroll
                for (int j = 0; j < 8; j++)
                    acc[i][j] += a[i] * bb[j];
        }
        __syncthreads();
    }

    #pragma unroll
    for (int i = 0; i < 8; i++) {
        int b = b0 + ty*8 + i;
        float4 o0 = make_float4(acc[i][0], acc[i][1], acc[i][2], acc[i][3]);
        float4 o1 = make_float4(acc[i][4], acc[i][5], acc[i][6], acc[i][7]);
        *(float4*)(out + b * DM + d0 + tx*8)     = o0;
        *(float4*)(out + b * DM + d0 + tx*8 + 4) = o1;
    }
}

// ---------------------------------------------------------------------------
// d_out layout (reference returns (output, gate, frobenius_norms)):
//   [0, 2048*2048)                     output, row-major (batch, d_model)
//   [2048*2048, +2048*64)              gate, row-major (batch, num_transforms)
//   [.., +64)                          frobenius_norms
// ---------------------------------------------------------------------------
extern "C" void kernel_launch(void* const* d_in, const int* in_sizes, int n_in,
                              void* d_out, int out_size)
{
    const float* x    = (const float*)d_in[0];  // (2048, 2048)
    const float* Vw   = (const float*)d_in[1];  // (64, 32, 2048)
    const float* Uw   = (const float*)d_in[2];  // (64, 2048, 32)
    const float* enc  = (const float*)d_in[3];  // (64, 2048)
    const float* bias = (const float*)d_in[4];  // (64,)

    float* out  = (float*)d_out;
    float* gate = out + BATCH * DM;
    float* frob = gate + BATCH * NT;

    gate_kernel<<<BATCH / 32, 256>>>(x, enc, bias, gate);
    norm_kernel<<<2 * NT, 256>>>(Uw, Vw);
    frob_kernel<<<1, NT>>>(frob);
    gemm_vx<<<dim3(DM / 128, BATCH / 128), 256>>>(x, Vw, gate);
    gemm_out<<<dim3(DM / 128, BATCH / 128), 256>>>(Uw, out);
}

// round 3
// speedup vs baseline: 2.1951x; 2.1951x over previous
#include <cuda_runtime.h>
#include <cuda_bf16.h>
#include <cstdint>

#define DM 2048   // d_model
#define BATCH 2048
#define NT 64     // num transforms
#define RK 32     // rank

// ---------------------------------------------------------------------------
// Static device scratch (no allocation allowed)
// ---------------------------------------------------------------------------
__device__ __nv_bfloat16 g_xh[BATCH * DM], g_xl[BATCH * DM];    // x hi/lo     [b][d]
__device__ __nv_bfloat16 g_vh[DM * DM],    g_vl[DM * DM];       // V_flat      [k][d]
__device__ __nv_bfloat16 g_wth[DM * DM],   g_wtl[DM * DM];      // Wt = U^T    [d][k]
__device__ __nv_bfloat16 g_gvh[BATCH * DM], g_gvl[BATCH * DM];  // gated Vx    [b][k]
__device__ float g_norms[2 * NT];

// ---------------------------------------------------------------------------
// PTX helpers (portable sm_80+ subset only; NO tcgen05 on this toolchain)
// ---------------------------------------------------------------------------
__device__ __forceinline__ uint32_t smem_u32(const void* p) {
    return (uint32_t)__cvta_generic_to_shared(p);
}

__device__ __forceinline__ void cp16(uint32_t dst, const void* src) {
    asm volatile("cp.async.cg.shared.global [%0], [%1], 16;\n" :: "r"(dst), "l"(src));
}
__device__ __forceinline__ void cp_commit() {
    asm volatile("cp.async.commit_group;\n" ::: "memory");
}
template<int N>
__device__ __forceinline__ void cp_wait() {
    asm volatile("cp.async.wait_group %0;\n" :: "n"(N) : "memory");
}

__device__ __forceinline__ void ldsm4(uint32_t* r, uint32_t addr) {
    asm volatile("ldmatrix.sync.aligned.m8n8.x4.shared.b16 {%0,%1,%2,%3}, [%4];"
                 : "=r"(r[0]), "=r"(r[1]), "=r"(r[2]), "=r"(r[3]) : "r"(addr));
}

__device__ __forceinline__ void mma_bf16(float* d, const uint32_t* a, const uint32_t* b) {
    asm volatile(
        "mma.sync.aligned.m16n8k16.row.col.f32.bf16.bf16.f32 "
        "{%0,%1,%2,%3}, {%4,%5,%6,%7}, {%8,%9}, {%0,%1,%2,%3};"
        : "+f"(d[0]), "+f"(d[1]), "+f"(d[2]), "+f"(d[3])
        : "r"(a[0]), "r"(a[1]), "r"(a[2]), "r"(a[3]), "r"(b[0]), "r"(b[1]));
}

// ---------------------------------------------------------------------------
// Gate kernel (fp32, exact): gate[b,n] = relu(x[b,:]·enc[n,:] - bias[n])
// ---------------------------------------------------------------------------
__global__ __launch_bounds__(256) void gate_kernel(
    const float* __restrict__ x, const float* __restrict__ enc,
    const float* __restrict__ bias, float* __restrict__ gate)
{
    __shared__ __align__(16) float As[32][36];
    __shared__ __align__(16) float Es[32][68];

    const int tid = threadIdx.x;
    const int tx = tid & 15, ty = tid >> 4;
    const int b0 = blockIdx.x * 32;
    const int f4 = tid & 7, lrow = tid >> 3;

    float acc[2][4];
    #pragma unroll
    for (int i = 0; i < 2; i++)
        #pragma unroll
        for (int j = 0; j < 4; j++) acc[i][j] = 0.0f;

    for (int d0 = 0; d0 < DM; d0 += 32) {
        {
            float4 v = *(const float4*)(x + (b0 + lrow) * DM + d0 + f4 * 4);
            As[f4*4+0][lrow] = v.x; As[f4*4+1][lrow] = v.y;
            As[f4*4+2][lrow] = v.z; As[f4*4+3][lrow] = v.w;
        }
        #pragma unroll
        for (int p = 0; p < 2; p++) {
            int row = p * 32 + lrow;
            float4 v = *(const float4*)(enc + row * DM + d0 + f4 * 4);
            Es[f4*4+0][row] = v.x; Es[f4*4+1][row] = v.y;
            Es[f4*4+2][row] = v.z; Es[f4*4+3][row] = v.w;
        }
        __syncthreads();
        #pragma unroll
        for (int kk = 0; kk < 32; kk++) {
            float a0 = As[kk][ty*2 + 0];
            float a1 = As[kk][ty*2 + 1];
            float4 e = *(const float4*)&Es[kk][tx*4];
            acc[0][0] += a0 * e.x; acc[0][1] += a0 * e.y;
            acc[0][2] += a0 * e.z; acc[0][3] += a0 * e.w;
            acc[1][0] += a1 * e.x; acc[1][1] += a1 * e.y;
            acc[1][2] += a1 * e.z; acc[1][3] += a1 * e.w;
        }
        __syncthreads();
    }
    #pragma unroll
    for (int i = 0; i < 2; i++) {
        int b = b0 + ty*2 + i;
        #pragma unroll
        for (int j = 0; j < 4; j++) {
            int n = tx*4 + j;
            float p = acc[i][j] - bias[n];
            gate[b * NT + n] = (p > 0.0f) ? p : 0.0f;
        }
    }
}

// ---------------------------------------------------------------------------
// Frobenius norms
// ---------------------------------------------------------------------------
__global__ __launch_bounds__(256) void norm_kernel(
    const float* __restrict__ Uw, const float* __restrict__ Vw)
{
    int bid = blockIdx.x;  // 0..127
    const float* base = (bid < NT) ? (Uw + (long)bid * (DM * RK))
                                   : (Vw + (long)(bid - NT) * (RK * DM));
    const float4* p4 = (const float4*)base;
    float s = 0.0f;
    for (int i = threadIdx.x; i < (DM * RK) / 4; i += 256) {
        float4 v = p4[i];
        s += v.x*v.x + v.y*v.y + v.z*v.z + v.w*v.w;
    }
    __shared__ float red[256];
    red[threadIdx.x] = s;
    __syncthreads();
    for (int off = 128; off > 0; off >>= 1) {
        if (threadIdx.x < off) red[threadIdx.x] += red[threadIdx.x + off];
        __syncthreads();
    }
    if (threadIdx.x == 0) g_norms[bid] = sqrtf(red[0]);
}

__global__ void frob_kernel(float* __restrict__ frob)
{
    int n = threadIdx.x;
    frob[n] = g_norms[n] * g_norms[NT + n] * (1.0f / 256.0f);
}

// ---------------------------------------------------------------------------
// Prep: split fp32 -> (hi, lo) bf16.  WHICH 0: x -> g_xh/g_xl, 1: V -> g_vh/g_vl
// ---------------------------------------------------------------------------
template<int WHICH>
__global__ __launch_bounds__(256) void prep_split(const float4* __restrict__ src)
{
    uint2* hi = (WHICH == 0) ? (uint2*)g_xh : (uint2*)g_vh;
    uint2* lo = (WHICH == 0) ? (uint2*)g_xl : (uint2*)g_vl;
    int i = blockIdx.x * 256 + threadIdx.x;
    float4 v = src[i];
    __nv_bfloat162 h01 = __floats2bfloat162_rn(v.x, v.y);
    __nv_bfloat162 h23 = __floats2bfloat162_rn(v.z, v.w);
    float l0 = v.x - __bfloat162float(__low2bfloat16(h01));
    float l1 = v.y - __bfloat162float(__high2bfloat16(h01));
    float l2 = v.z - __bfloat162float(__low2bfloat16(h23));
    float l3 = v.w - __bfloat162float(__high2bfloat16(h23));
    __nv_bfloat162 q01 = __floats2bfloat162_rn(l0, l1);
    __nv_bfloat162 q23 = __floats2bfloat162_rn(l2, l3);
    hi[i] = make_uint2(*(uint32_t*)&h01, *(uint32_t*)&h23);
    lo[i] = make_uint2(*(uint32_t*)&q01, *(uint32_t*)&q23);
}

// ---------------------------------------------------------------------------
// Prep: transpose U (64, 2048, 32) into Wt[d][k] (k = n*32 + r), hi/lo bf16
// ---------------------------------------------------------------------------
__global__ __launch_bounds__(256) void prep_u(const float* __restrict__ Uw)
{
    const int n  = blockIdx.x;
    const int d0 = blockIdx.y * 128;
    #pragma unroll
    for (int it = 0; it < 4; it++) {
        int lin = threadIdx.x + it * 256;
        int dl = lin >> 3;
        int q  = lin & 7;
        float4 v = *(const float4*)(Uw + ((long)n * DM + d0 + dl) * RK + q * 4);
        __nv_bfloat162 h01 = __floats2bfloat162_rn(v.x, v.y);
        __nv_bfloat162 h23 = __floats2bfloat162_rn(v.z, v.w);
        float l0 = v.x - __bfloat162float(__low2bfloat16(h01));
        float l1 = v.y - __bfloat162float(__high2bfloat16(h01));
        float l2 = v.z - __bfloat162float(__low2bfloat16(h23));
        float l3 = v.w - __bfloat162float(__high2bfloat16(h23));
        __nv_bfloat162 q01 = __floats2bfloat162_rn(l0, l1);
        __nv_bfloat162 q23 = __floats2bfloat162_rn(l2, l3);
        long o = (long)(d0 + dl) * DM + n * RK + q * 4;
        *(uint2*)(g_wth + o) = make_uint2(*(uint32_t*)&h01, *(uint32_t*)&h23);
        *(uint2*)(g_wtl + o) = make_uint2(*(uint32_t*)&q01, *(uint32_t*)&q23);
    }
}

// ---------------------------------------------------------------------------
// Warp-MMA GEMM (mma.sync m16n8k16 bf16, fp32 acc), hi/lo 3-pass split.
// D[m,n] = sum_k A[m,k]*B[n,k]  (A row-major K-contig, B row-major K-contig)
// Tile: BM=128, BN=128, BK=32. 8 warps (4x2), warp tile 32x64.
// Smem: per stage Ah(8K) Al(8K) Bh(8K) Bl(8K) = 32KB, 2 stages = 64KB dyn.
// SW64 swizzle on 64-byte rows: sw = row*64 + (kbyte ^ ((row&6)<<3)).
// MODE 0: A=x, B=Vflat; epilogue *gate -> GVx hi/lo bf16
// MODE 1: A=GVx, B=Wt;   epilogue fp32 -> out
// ---------------------------------------------------------------------------
#define MMA_SMEM 65536

template<int MODE>
__global__ __launch_bounds__(256, 1) void mma_gemm(const float* __restrict__ gate,
                                                   float* __restrict__ outf)
{
    extern __shared__ char sm[];
    const uint32_t sbase = smem_u32(sm);

    const int tid  = threadIdx.x;
    const int wid  = tid >> 5;
    const int lane = tid & 31;
    const int n0 = blockIdx.x * 128;
    const int b0 = blockIdx.y * 128;
    const int wm = (wid & 3) * 32;    // warp m offset
    const int wn = (wid >> 2) * 64;   // warp n offset

    const __nv_bfloat16* __restrict__ Ah = (MODE == 0) ? g_xh : g_gvh;
    const __nv_bfloat16* __restrict__ Al = (MODE == 0) ? g_xl : g_gvl;
    const __nv_bfloat16* __restrict__ Bh = (MODE == 0) ? g_vh : g_wth;
    const __nv_bfloat16* __restrict__ Bl = (MODE == 0) ? g_vl : g_wtl;

    float d[2][8][4];
    #pragma unroll
    for (int i = 0; i < 2; i++)
        #pragma unroll
        for (int j = 0; j < 8; j++)
            #pragma unroll
            for (int r = 0; r < 4; r++) d[i][j][r] = 0.0f;

    // per-thread load coords (2 iters x 4 tiles of 16B cp.async)
    const int r0c = tid >> 2;            // rows 0..63   (it 0)
    const int r1c = 64 + (tid >> 2);     // rows 64..127 (it 1)
    const int cbe = (tid & 3) * 8;       // element offset in k (8 bf16 = 16B)
    const uint32_t sw0 = (uint32_t)r0c * 64 + (((tid & 3) * 16) ^ ((r0c & 6) << 3));
    const uint32_t sw1 = (uint32_t)r1c * 64 + (((tid & 3) * 16) ^ ((r1c & 6) << 3));

    auto issue = [&](int c) {
        const uint32_t st = sbase + (uint32_t)(c & 1) * 32768u;
        const int kb = c * 32;
        const size_t ga0 = (size_t)(b0 + r0c) * DM + kb + cbe;
        const size_t ga1 = (size_t)(b0 + r1c) * DM + kb + cbe;
        const size_t gb0 = (size_t)(n0 + r0c) * DM + kb + cbe;
        const size_t gb1 = (size_t)(n0 + r1c) * DM + kb + cbe;
        cp16(st + sw0,          Ah + ga0);
        cp16(st + sw1,          Ah + ga1);
        cp16(st + 8192 + sw0,   Al + ga0);
        cp16(st + 8192 + sw1,   Al + ga1);
        cp16(st + 16384 + sw0,  Bh + gb0);
        cp16(st + 16384 + sw1,  Bh + gb1);
        cp16(st + 24576 + sw0,  Bl + gb0);
        cp16(st + 24576 + sw1,  Bl + gb1);
        cp_commit();
    };

    // ldmatrix lane address components (constant per thread)
    const int a_row = wm + (lane & 15);             // + mb*16
    const int a_kc  = (lane >> 4) * 16;             // byte offset within k16 (x4: k-half select)
    const int b_row = wn + (lane & 7) + ((lane >> 4) << 3);   // + q*16
    const int b_kc  = ((lane >> 3) & 1) * 16;

    issue(0);

    for (int c = 0; c < 64; ++c) {
        if (c < 63) issue(c + 1);
        if (c < 63) cp_wait<1>(); else cp_wait<0>();
        __syncthreads();

        const uint32_t st = sbase + (uint32_t)(c & 1) * 32768u;

        #pragma unroll
        for (int k16 = 0; k16 < 2; ++k16) {
            const int koff = k16 * 32;  // bytes

            uint32_t ah[2][4], al[2][4];
            #pragma unroll
            for (int mb = 0; mb < 2; ++mb) {
                int row = a_row + mb * 16;
                uint32_t sw = (uint32_t)row * 64 + (uint32_t)((koff + a_kc) ^ ((row & 6) << 3));
                ldsm4(ah[mb], st + sw);
                ldsm4(al[mb], st + 8192 + sw);
            }
            uint32_t bh[4][4], bl[4][4];
            #pragma unroll
            for (int q = 0; q < 4; ++q) {
                int row = b_row + q * 16;
                uint32_t sw = (uint32_t)row * 64 + (uint32_t)((koff + b_kc) ^ ((row & 6) << 3));
                ldsm4(bh[q], st + 16384 + sw);
                ldsm4(bl[q], st + 24576 + sw);
            }
            #pragma unroll
            for (int mb = 0; mb < 2; ++mb) {
                #pragma unroll
                for (int q = 0; q < 4; ++q) {
                    mma_bf16(d[mb][q*2],   ah[mb], &bh[q][0]);   // hi*hi
                    mma_bf16(d[mb][q*2+1], ah[mb], &bh[q][2]);
                    mma_bf16(d[mb][q*2],   ah[mb], &bl[q][0]);   // hi*lo
                    mma_bf16(d[mb][q*2+1], ah[mb], &bl[q][2]);
                    mma_bf16(d[mb][q*2],   al[mb], &bh[q][0]);   // lo*hi
                    mma_bf16(d[mb][q*2+1], al[mb], &bh[q][2]);
                }
            }
        }
        __syncthreads();
    }

    // Epilogue. Lane mapping: g = lane>>2 (row within 8), t = lane&3 (col pair)
    const int g = lane >> 2, t = lane & 3;
    #pragma unroll
    for (int mb = 0; mb < 2; ++mb) {
        #pragma unroll
        for (int half = 0; half < 2; ++half) {
            const int b = b0 + wm + mb * 16 + g + half * 8;
            #pragma unroll
            for (int ni = 0; ni < 8; ++ni) {
                const int colg = n0 + wn + ni * 8 + t * 2;
                if (MODE == 0) {
                    const int ntr = (n0 + wn + ni * 8) >> 5;
                    const float gv = __ldg(&gate[b * NT + ntr]);
                    float f0 = d[mb][ni][half * 2 + 0] * gv;
                    float f1 = d[mb][ni][half * 2 + 1] * gv;
                    __nv_bfloat162 hv = __floats2bfloat162_rn(f0, f1);
                    float l0 = f0 - __bfloat162float(__low2bfloat16(hv));
                    float l1 = f1 - __bfloat162float(__high2bfloat16(hv));
                    __nv_bfloat162 lv = __floats2bfloat162_rn(l0, l1);
                    *(uint32_t*)(g_gvh + (size_t)b * DM + colg) = *(uint32_t*)&hv;
                    *(uint32_t*)(g_gvl + (size_t)b * DM + colg) = *(uint32_t*)&lv;
                } else {
                    float2 o = make_float2(d[mb][ni][half * 2 + 0],
                                           d[mb][ni][half * 2 + 1]);
                    *(float2*)(outf + (size_t)b * DM + colg) = o;
                }
            }
        }
    }
}

// ---------------------------------------------------------------------------
// d_out layout: [output 2048*2048 | gate 2048*64 | frob 64]
// ---------------------------------------------------------------------------
extern "C" void kernel_launch(void* const* d_in, const int* in_sizes, int n_in,
                              void* d_out, int out_size)
{
    const float* x    = (const float*)d_in[0];  // (2048, 2048)
    const float* Vw   = (const float*)d_in[1];  // (64, 32, 2048)
    const float* Uw   = (const float*)d_in[2];  // (64, 2048, 32)
    const float* enc  = (const float*)d_in[3];  // (64, 2048)
    const float* bias = (const float*)d_in[4];  // (64,)

    float* out  = (float*)d_out;
    float* gate = out + BATCH * DM;
    float* frob = gate + BATCH * NT;

    cudaFuncSetAttribute(mma_gemm<0>, cudaFuncAttributeMaxDynamicSharedMemorySize, MMA_SMEM);
    cudaFuncSetAttribute(mma_gemm<1>, cudaFuncAttributeMaxDynamicSharedMemorySize, MMA_SMEM);

    gate_kernel<<<BATCH / 32, 256>>>(x, enc, bias, gate);
    prep_split<0><<<(BATCH * DM) / 4 / 256, 256>>>((const float4*)x);
    prep_split<1><<<(DM * DM) / 4 / 256, 256>>>((const float4*)Vw);
    prep_u<<<dim3(NT, DM / 128), 256>>>(Uw);
    norm_kernel<<<2 * NT, 256>>>(Uw, Vw);
    frob_kernel<<<1, NT>>>(frob);

    mma_gemm<0><<<dim3(DM / 128, BATCH / 128), 256, MMA_SMEM>>>(gate, nullptr);
    mma_gemm<1><<<dim3(DM / 128, BATCH / 128), 256, MMA_SMEM>>>(nullptr, out);
}